// round 14
// baseline (speedup 1.0000x reference)
#include <cuda_runtime.h>
#include <cuda_bf16.h>
#include <math.h>

// EdgeEmbeddingBlock: out_r[b,k,i,j] = radial[b,i] * na[b,k] * ylm_r[b,j]
//                     out_i[b,k,i,j] = radial[b,i] * na[b,k] * ylm_i[b,j]
// E=60000, K=10, NMAX=8, J=16. Output [combined_r | combined_i], 614 MB written.
//
// FINAL converged config (86.2-86.9us band = HBM write-path floor, ~6.35 TB/s
// wire / ~7.1 TB/s effective): register-resident expansion, 1 warp/edge,
// __stcs STG.128 streams, 256-thread blocks, 32-bit output indexing, split
// r/i store passes. Falsified alternatives (12 experiments): persistence,
// occupancy 8, block 128/512, write-back, __stwt, STG.256, smem staging,
// interleaved store streams — all neutral or worse. Traffic is irreducible;
// kernel is at >=97% of the measured machine ceiling for this store pattern.

#define KATTR 10
#define F4_PER_EDGE 320u         // 1280 floats / 4

#define SEL4(g,a,b,c,d) ((g)==0?(a):((g)==1?(b):((g)==2?(c):(d))))

__global__ __launch_bounds__(256, 6)
void edge_embed_kernel(const int* __restrict__ edge_index,
                       const float* __restrict__ lens,
                       const float* __restrict__ vecs,
                       const float* __restrict__ attrs,
                       float* __restrict__ out,
                       int E)
{
    const int warp = threadIdx.x >> 5;
    const int lane = threadIdx.x & 31;
    const int e = blockIdx.x * 8 + warp;
    if (e >= E) return;

    // ---- per-edge scalars (broadcast loads) ----
    const float x  = lens[e];
    const float vx = vecs[3 * e + 0];
    const float vy = vecs[3 * e + 1];
    const float vz = vecs[3 * e + 2];
    const int sender = edge_index[e];   // edge_index[0, e]

    // lanes 0..9: node attrs for shuffle distribution
    float na_v = 0.0f;
    if (lane < KATTR) na_v = attrs[sender * KATTR + lane];

    // ---- radial: each lane computes rad[lane>>2] (poly cutoff p=6, R_CUT=5) ----
    const float u  = x * 0.2f;
    const float u2 = u * u, u3 = u2 * u;
    const float u6 = u3 * u3, u7 = u6 * u, u8 = u7 * u;
    float env = 1.0f - 28.0f * u6 + 48.0f * u7 - 21.0f * u8;
    env = (u < 1.0f) ? env : 0.0f;
    const float base = 0.63245553203f * env / x;          // sqrt(2/5) * env / x
    const float w = (float)((lane >> 2) + 1) * 0.62831853071f;  // n*pi/R_CUT
    const float r_l = base * sinf(w * x);

    // ---- zonal harmonics (all lanes, straight-line) ----
    const float nrm = sqrtf(vx * vx + vy * vy + vz * vz);
    const float inv = 1.0f / fmaxf(nrm, 1e-9f);
    const float ux = vx * inv, uy = vy * inv, uz = vz * inv;
    const float ct  = uz;
    const float st2 = fmaxf(1.0f - ct * ct, 0.0f);
    const float st  = sqrtf(st2);
    const float rxy = sqrtf(ux * ux + uy * uy);
    float c1, s1;
    if (rxy > 0.0f) { const float ir = 1.0f / rxy; c1 = ux * ir; s1 = uy * ir; }
    else            { c1 = 1.0f; s1 = 0.0f; }
    const float c2 = 2.0f * c1 * c1 - 1.0f;
    const float s2 = 2.0f * s1 * c1;
    const float c3 = c1 * c2 - s1 * s2;
    const float s3 = s1 * c2 + c1 * s2;

    const float P11 = -st;
    const float P22 = 3.0f * st2;
    const float P33 = -15.0f * st2 * st;
    const float P21 = -3.0f * ct * st;
    const float P32 = 15.0f * ct * st2;
    const float P20 = 1.5f * ct * ct - 0.5f;
    const float P31 = 0.5f * (5.0f * ct * P21 + 3.0f * st);
    const float P30 = ct * (2.5f * ct * ct - 1.5f);

    const float n00 = 0.28209479177f;
    const float n10 = 0.48860251190f, n11 = 0.34549414947f;
    const float n20 = 0.63078313051f, n21 = 0.25751613469f, n22 = 0.12875806734f;
    const float n30 = 0.74635266518f, n31 = 0.21545345607f, n32 = 0.06813236028f,
                n33 = 0.02781492157f;

    const float a  = n11 * P11;
    const float b1 = n21 * P21, b2 = n22 * P22;
    const float d1 = n31 * P31, d2 = n32 * P32, d3 = n33 * P33;

    // ylm groups (j = 4g .. 4g+3), select this lane's group g = lane & 3
    const int g = lane & 3;
    float4 yr4, yi4;
    yr4.x = SEL4(g, n00,       b2 * c2,   b2 * c2,  n30 * P30);
    yr4.y = SEL4(g, -a * c1,  -b1 * c1,  -d3 * c3,  d1 * c1);
    yr4.z = SEL4(g, n10 * ct,  n20 * P20, d2 * c2,  d2 * c2);
    yr4.w = SEL4(g, a * c1,    b1 * c1,  -d1 * c1,  d3 * c3);
    yi4.x = SEL4(g, 0.0f,     -b2 * s2,   b2 * s2,  0.0f);
    yi4.y = SEL4(g, a * s1,    b1 * s1,   d3 * s3,  d1 * s1);
    yi4.z = SEL4(g, 0.0f,      0.0f,     -d2 * s2,  d2 * s2);
    yi4.w = SEL4(g, a * s1,    b1 * s1,   d1 * s1,  d3 * s3);

    // ---- per-k scales (shuffled once, reused by both passes) ----
    float sk[KATTR];
    #pragma unroll
    for (int it = 0; it < KATTR; ++it)
        sk[it] = r_l * __shfl_sync(0xffffffffu, na_v, it);

    // ---- 32-bit indexed, immediate-offset streaming stores ----
    float4* __restrict__ out4 = (float4*)out;
    float4* __restrict__ pr = out4 + ((unsigned)e * F4_PER_EDGE + (unsigned)lane);
    float4* __restrict__ pi = out4 + (((unsigned)E + (unsigned)e) * F4_PER_EDGE + (unsigned)lane);

    #pragma unroll
    for (int it = 0; it < KATTR; ++it) {
        const float s = sk[it];
        float4 orr = make_float4(s * yr4.x, s * yr4.y, s * yr4.z, s * yr4.w);
        __stcs(pr + 32 * it, orr);
    }
    #pragma unroll
    for (int it = 0; it < KATTR; ++it) {
        const float s = sk[it];
        float4 oii = make_float4(s * yi4.x, s * yi4.y, s * yi4.z, s * yi4.w);
        __stcs(pi + 32 * it, oii);
    }
}

extern "C" void kernel_launch(void* const* d_in, const int* in_sizes, int n_in,
                              void* d_out, int out_size)
{
    const int*   edge_index = (const int*)d_in[0];    // (2, E) int32
    const float* lens       = (const float*)d_in[1];  // (E, 1) f32
    const float* vecs       = (const float*)d_in[2];  // (E, 3) f32
    const float* attrs      = (const float*)d_in[3];  // (N_NODES, 10) f32
    float* out = (float*)d_out;

    const int E = in_sizes[1];   // edge_lenghts element count
    const int blocks = (E + 7) / 8;
    edge_embed_kernel<<<blocks, 256>>>(edge_index, lens, vecs, attrs, out, E);
}

// round 15
// speedup vs baseline: 1.0179x; 1.0179x over previous
#include <cuda_runtime.h>
#include <cuda_bf16.h>
#include <math.h>

// EdgeEmbeddingBlock: out_r[b,k,i,j] = radial[b,i] * na[b,k] * ylm_r[b,j]
//                     out_i[b,k,i,j] = radial[b,i] * na[b,k] * ylm_i[b,j]
// E=60000, K=10, NMAX=8, J=16. Output [combined_r | combined_i], 614 MB written.
//
// R15 experiment on the converged config: split grid so each warp writes ONLY
// one half (r or i) — halves the number of live DRAM write streams (one per
// warp instead of two 307MB apart) and doubles edge-level parallelism.
// Setup math recomputed per half (compute is 13% busy; free).

#define KATTR 10
#define F4_PER_EDGE 320u         // 1280 floats / 4

#define SEL4(g,a,b,c,d) ((g)==0?(a):((g)==1?(b):((g)==2?(c):(d))))

__global__ __launch_bounds__(256, 6)
void edge_embed_kernel(const int* __restrict__ edge_index,
                       const float* __restrict__ lens,
                       const float* __restrict__ vecs,
                       const float* __restrict__ attrs,
                       float* __restrict__ out,
                       int E, int bhalf)
{
    const int warp = threadIdx.x >> 5;
    const int lane = threadIdx.x & 31;
    const bool imag = (blockIdx.x >= (unsigned)bhalf);
    const int blk = imag ? (blockIdx.x - bhalf) : blockIdx.x;
    const int e = blk * 8 + warp;
    if (e >= E) return;

    // ---- per-edge scalars (broadcast loads) ----
    const float x  = lens[e];
    const float vx = vecs[3 * e + 0];
    const float vy = vecs[3 * e + 1];
    const float vz = vecs[3 * e + 2];
    const int sender = edge_index[e];   // edge_index[0, e]

    // lanes 0..9: node attrs for shuffle distribution
    float na_v = 0.0f;
    if (lane < KATTR) na_v = attrs[sender * KATTR + lane];

    // ---- radial: each lane computes rad[lane>>2] (poly cutoff p=6, R_CUT=5) ----
    const float u  = x * 0.2f;
    const float u2 = u * u, u3 = u2 * u;
    const float u6 = u3 * u3, u7 = u6 * u, u8 = u7 * u;
    float env = 1.0f - 28.0f * u6 + 48.0f * u7 - 21.0f * u8;
    env = (u < 1.0f) ? env : 0.0f;
    const float base = 0.63245553203f * env / x;          // sqrt(2/5) * env / x
    const float w = (float)((lane >> 2) + 1) * 0.62831853071f;  // n*pi/R_CUT
    const float r_l = base * sinf(w * x);

    // ---- zonal harmonics (all lanes, straight-line) ----
    const float nrm = sqrtf(vx * vx + vy * vy + vz * vz);
    const float inv = 1.0f / fmaxf(nrm, 1e-9f);
    const float ux = vx * inv, uy = vy * inv, uz = vz * inv;
    const float ct  = uz;
    const float st2 = fmaxf(1.0f - ct * ct, 0.0f);
    const float st  = sqrtf(st2);
    const float rxy = sqrtf(ux * ux + uy * uy);
    float c1, s1;
    if (rxy > 0.0f) { const float ir = 1.0f / rxy; c1 = ux * ir; s1 = uy * ir; }
    else            { c1 = 1.0f; s1 = 0.0f; }
    const float c2 = 2.0f * c1 * c1 - 1.0f;
    const float s2 = 2.0f * s1 * c1;
    const float c3 = c1 * c2 - s1 * s2;
    const float s3 = s1 * c2 + c1 * s2;

    const float P11 = -st;
    const float P22 = 3.0f * st2;
    const float P33 = -15.0f * st2 * st;
    const float P21 = -3.0f * ct * st;
    const float P32 = 15.0f * ct * st2;
    const float P20 = 1.5f * ct * ct - 0.5f;
    const float P31 = 0.5f * (5.0f * ct * P21 + 3.0f * st);
    const float P30 = ct * (2.5f * ct * ct - 1.5f);

    const float n00 = 0.28209479177f;
    const float n10 = 0.48860251190f, n11 = 0.34549414947f;
    const float n20 = 0.63078313051f, n21 = 0.25751613469f, n22 = 0.12875806734f;
    const float n30 = 0.74635266518f, n31 = 0.21545345607f, n32 = 0.06813236028f,
                n33 = 0.02781492157f;

    const float a  = n11 * P11;
    const float b1 = n21 * P21, b2 = n22 * P22;
    const float d1 = n31 * P31, d2 = n32 * P32, d3 = n33 * P33;

    // this warp's half only: ylm group for j = 4g..4g+3, g = lane & 3
    const int g = lane & 3;
    float4 y4;
    if (!imag) {
        y4.x = SEL4(g, n00,       b2 * c2,   b2 * c2,  n30 * P30);
        y4.y = SEL4(g, -a * c1,  -b1 * c1,  -d3 * c3,  d1 * c1);
        y4.z = SEL4(g, n10 * ct,  n20 * P20, d2 * c2,  d2 * c2);
        y4.w = SEL4(g, a * c1,    b1 * c1,  -d1 * c1,  d3 * c3);
    } else {
        y4.x = SEL4(g, 0.0f,     -b2 * s2,   b2 * s2,  0.0f);
        y4.y = SEL4(g, a * s1,    b1 * s1,   d3 * s3,  d1 * s1);
        y4.z = SEL4(g, 0.0f,      0.0f,     -d2 * s2,  d2 * s2);
        y4.w = SEL4(g, a * s1,    b1 * s1,   d1 * s1,  d3 * s3);
    }

    // ---- single contiguous stream: 10 STG.128 per lane ----
    float4* __restrict__ out4 = (float4*)out;
    const unsigned half_off = imag ? (unsigned)E * F4_PER_EDGE : 0u;
    float4* __restrict__ p = out4 + (half_off + (unsigned)e * F4_PER_EDGE + (unsigned)lane);

    #pragma unroll
    for (int it = 0; it < KATTR; ++it) {
        const float s = r_l * __shfl_sync(0xffffffffu, na_v, it);
        float4 o = make_float4(s * y4.x, s * y4.y, s * y4.z, s * y4.w);
        __stcs(p + 32 * it, o);
    }
}

extern "C" void kernel_launch(void* const* d_in, const int* in_sizes, int n_in,
                              void* d_out, int out_size)
{
    const int*   edge_index = (const int*)d_in[0];    // (2, E) int32
    const float* lens       = (const float*)d_in[1];  // (E, 1) f32
    const float* vecs       = (const float*)d_in[2];  // (E, 3) f32
    const float* attrs      = (const float*)d_in[3];  // (N_NODES, 10) f32
    float* out = (float*)d_out;

    const int E = in_sizes[1];   // edge_lenghts element count
    const int bhalf = (E + 7) / 8;
    edge_embed_kernel<<<2 * bhalf, 256>>>(edge_index, lens, vecs, attrs, out, E, bhalf);
}